// round 1
// baseline (speedup 1.0000x reference)
#include <cuda_runtime.h>
#include <math.h>

#define BB 64
#define NN 4096
#define DD 128
#define SS 65536
#define KTOP 16

typedef unsigned long long ull;

// ---------------- scratch (device globals; allocation-free) ----------------
__device__ float g_wt[DD * DD];          // conv_w transposed: [d][e]
__device__ float g_mt[(size_t)DD * SS];  // normalized memory^T: [d][s]   (32 MB)
__device__ float g_qpart[BB * 32 * DD];  // per-tile partial gelu sums    (1 MB)
__device__ float g_qt[DD * BB];          // normalized q^T: [d][b]
__device__ float g_sim[(size_t)BB * SS]; // cosine sims                    (16 MB)
__device__ float g_proto[BB * DD];

// ---------------- helpers ----------------
__device__ __forceinline__ ull ffma2(ull a, ull b, ull c) {
    ull d;
    asm("fma.rn.f32x2 %0, %1, %2, %3;" : "=l"(d) : "l"(a), "l"(b), "l"(c));
    return d;
}
__device__ __forceinline__ ull dup2(float x) {
    ull d;
    asm("mov.b64 %0, {%1, %1};" : "=l"(d) : "f"(x));
    return d;
}
__device__ __forceinline__ void unpack2(ull v, float& lo, float& hi) {
    asm("mov.b64 {%0, %1}, %2;" : "=f"(lo), "=f"(hi) : "l"(v));
}
__device__ __forceinline__ float gelu_exact(float z) {
    return 0.5f * z * (1.0f + erff(z * 0.70710678118654752f));
}

// ---------------- K0: transpose conv_w -> g_wt ----------------
__global__ void k0_wt(const float* __restrict__ w) {
    int i = blockIdx.x * 256 + threadIdx.x;       // 16384 elems
    float v = w[i];                               // coalesced read [e][d]
    int e = i >> 7, d = i & 127;
    g_wt[d * 128 + e] = v;                        // scattered write (tiny)
}

// ---------------- K1: normalize+transpose memory -> g_mt ----------------
__global__ void __launch_bounds__(256) k1_mt(const float* __restrict__ mem) {
    __shared__ float tile[64][129];
    __shared__ float inv[64];
    int s0 = blockIdx.x * 64;
    int tid = threadIdx.x;

    int c = tid & 31, r0 = tid >> 5;              // 8 rows per pass
    #pragma unroll
    for (int it = 0; it < 8; ++it) {
        int r = r0 + it * 8;
        float4 v = *(const float4*)&mem[(size_t)(s0 + r) * 128 + c * 4];
        tile[r][c * 4 + 0] = v.x; tile[r][c * 4 + 1] = v.y;
        tile[r][c * 4 + 2] = v.z; tile[r][c * 4 + 3] = v.w;
    }
    __syncthreads();
    if (tid < 64) {
        float acc = 0.f;
        #pragma unroll 8
        for (int k = 0; k < 128; ++k) { float t = tile[tid][k]; acc = fmaf(t, t, acc); }
        inv[tid] = 1.0f / fmaxf(sqrtf(acc), 1e-12f);
    }
    __syncthreads();
    int r = tid & 63, kg = tid >> 6;              // 4 k per pass
    float iv = inv[r];
    #pragma unroll
    for (int it = 0; it < 32; ++it) {
        int k = kg + it * 4;
        g_mt[(size_t)k * SS + s0 + r] = tile[r][k] * iv;  // coalesced over r
    }
}

// ---------------- K2: fused conv1d+GeLU+sum-over-n (SGEMM, f32x2) -------
// tile: 128 positions x 128 outputs, K=128 in two 64-slabs.
// thread (tm,tn): m in [tm*8, tm*8+8), e in {tn*4..+3} U {64+tn*4..+3}
__global__ void __launch_bounds__(256, 2) k2_gemm(const float* __restrict__ x,
                                                  const float* __restrict__ bias) {
    extern __shared__ float sm[];
    float* ws = sm;               // [128][128] w^T (k-major, e contiguous)
    float* xs = sm + 16384;       // [128][65]  x tile (m-major, padded)

    int tid = threadIdx.x;
    int tile = blockIdx.x;        // 0..2047
    int b = tile >> 5;
    int p0 = tile << 7;

    // stage w^T (already transposed in gmem -> plain coalesced copy)
    {
        const float4* src = (const float4*)g_wt;
        float4* dst = (float4*)ws;
        #pragma unroll
        for (int i = tid; i < 4096; i += 256) dst[i] = src[i];
    }

    int tm = tid >> 4, tn = tid & 15;

    float bs[8];
    #pragma unroll
    for (int j = 0; j < 4; ++j) {
        bs[j]     = bias[tn * 4 + j];
        bs[4 + j] = bias[64 + tn * 4 + j];
    }

    ull acc[8][4];
    #pragma unroll
    for (int i = 0; i < 8; ++i)
        #pragma unroll
        for (int j = 0; j < 4; ++j) acc[i][j] = 0ull;

    for (int ks = 0; ks < 2; ++ks) {
        __syncthreads();
        // load x slab: rows 0..127, cols ks*64..+63
        {
            int c = tid & 15, r = tid >> 4;       // 16 rows per pass
            #pragma unroll
            for (int it = 0; it < 8; ++it) {
                int row = r + it * 16;
                float4 v = *(const float4*)&x[(size_t)(p0 + row) * 128 + ks * 64 + c * 4];
                float* d = &xs[row * 65 + c * 4];
                d[0] = v.x; d[1] = v.y; d[2] = v.z; d[3] = v.w;
            }
        }
        __syncthreads();

        #pragma unroll 4
        for (int k = 0; k < 64; ++k) {
            const float* wrow = ws + (ks * 64 + k) * 128;
            ulonglong2 w0 = *(const ulonglong2*)(wrow + tn * 4);
            ulonglong2 w1 = *(const ulonglong2*)(wrow + 64 + tn * 4);
            #pragma unroll
            for (int i = 0; i < 8; ++i) {
                ull ad = dup2(xs[(tm * 8 + i) * 65 + k]);
                acc[i][0] = ffma2(ad, w0.x, acc[i][0]);
                acc[i][1] = ffma2(ad, w0.y, acc[i][1]);
                acc[i][2] = ffma2(ad, w1.x, acc[i][2]);
                acc[i][3] = ffma2(ad, w1.y, acc[i][3]);
            }
        }
    }

    // epilogue: gelu(feat + bias), sum over the 8 m's of this thread
    float es[8];
    #pragma unroll
    for (int j = 0; j < 8; ++j) es[j] = 0.f;
    #pragma unroll
    for (int i = 0; i < 8; ++i) {
        #pragma unroll
        for (int j = 0; j < 4; ++j) {
            float lo, hi;
            unpack2(acc[i][j], lo, hi);
            int base = (j >> 1) * 4 + (j & 1) * 2;   // 0,2,4,6
            es[base]     += gelu_exact(lo + bs[base]);
            es[base + 1] += gelu_exact(hi + bs[base + 1]);
        }
    }

    __syncthreads();                 // done with xs; reuse as reduction buffer
    float* red = xs;                 // [16][128]
    #pragma unroll
    for (int j = 0; j < 4; ++j) {
        red[tm * 128 + tn * 4 + j]      = es[j];
        red[tm * 128 + 64 + tn * 4 + j] = es[4 + j];
    }
    __syncthreads();
    #pragma unroll
    for (int off = 8; off; off >>= 1) {
        if (tm < off) {
            #pragma unroll
            for (int j = 0; j < 4; ++j) {
                red[tm * 128 + tn * 4 + j]      += red[(tm + off) * 128 + tn * 4 + j];
                red[tm * 128 + 64 + tn * 4 + j] += red[(tm + off) * 128 + 64 + tn * 4 + j];
            }
        }
        __syncthreads();
    }
    if (tid < 128)
        g_qpart[((size_t)b * 32 + (tile & 31)) * 128 + tid] = red[tid];
}

// ---------------- K3: finalize q (deterministic sum) + normalize + T ----
__global__ void k3_q() {
    int b = blockIdx.x, e = threadIdx.x;   // 64 blocks x 128 threads
    float q = 0.f;
    const float* p = g_qpart + (size_t)b * 32 * 128 + e;
    #pragma unroll
    for (int t = 0; t < 32; ++t) q += p[t * 128];
    __shared__ float sr[128];
    sr[e] = q * q;
    __syncthreads();
    for (int off = 64; off; off >>= 1) {
        if (e < off) sr[e] += sr[e + off];
        __syncthreads();
    }
    float inv = 1.0f / fmaxf(sqrtf(sr[0]), 1e-12f);
    g_qt[e * 64 + b] = q * inv;            // transposed, normalized
}

// ---------------- K4: sim = qn @ mn^T  (64 x 65536 GEMM, f32x2) ---------
// tile: 64 b x 256 s; thread (tm,tn): b in [tm*4,+4), s-slots {tn+16g}
__global__ void __launch_bounds__(256) k4_sim() {
    __shared__ float qs[128 * 64];   // [k][b]
    __shared__ float ms[8 * 256];    // k-slab of m^T
    int tid = threadIdx.x;
    int s0 = blockIdx.x * 256;

    for (int i = tid; i < 8192; i += 256) qs[i] = g_qt[i];

    int tm = tid >> 4, tn = tid & 15;
    ull acc[4][8];
    #pragma unroll
    for (int i = 0; i < 4; ++i)
        #pragma unroll
        for (int j = 0; j < 8; ++j) acc[i][j] = 0ull;

    for (int ks = 0; ks < 16; ++ks) {
        __syncthreads();
        {
            int c = tid & 63, r = tid >> 6;
            #pragma unroll
            for (int it = 0; it < 2; ++it) {
                int r2 = r + it * 4;
                *(float4*)&ms[r2 * 256 + c * 4] =
                    *(const float4*)&g_mt[(size_t)(ks * 8 + r2) * SS + s0 + c * 4];
            }
        }
        __syncthreads();
        #pragma unroll
        for (int k = 0; k < 8; ++k) {
            float4 av = *(const float4*)&qs[(ks * 8 + k) * 64 + tm * 4];
            ull a0 = dup2(av.x), a1 = dup2(av.y), a2 = dup2(av.z), a3 = dup2(av.w);
            const float* mrow = ms + k * 256;
            #pragma unroll
            for (int g = 0; g < 4; ++g) {
                ulonglong2 bv = *(const ulonglong2*)(mrow + (tn + g * 16) * 4);
                acc[0][g * 2 + 0] = ffma2(a0, bv.x, acc[0][g * 2 + 0]);
                acc[0][g * 2 + 1] = ffma2(a0, bv.y, acc[0][g * 2 + 1]);
                acc[1][g * 2 + 0] = ffma2(a1, bv.x, acc[1][g * 2 + 0]);
                acc[1][g * 2 + 1] = ffma2(a1, bv.y, acc[1][g * 2 + 1]);
                acc[2][g * 2 + 0] = ffma2(a2, bv.x, acc[2][g * 2 + 0]);
                acc[2][g * 2 + 1] = ffma2(a2, bv.y, acc[2][g * 2 + 1]);
                acc[3][g * 2 + 0] = ffma2(a3, bv.x, acc[3][g * 2 + 0]);
                acc[3][g * 2 + 1] = ffma2(a3, bv.y, acc[3][g * 2 + 1]);
            }
        }
    }
    #pragma unroll
    for (int i = 0; i < 4; ++i) {
        int b = tm * 4 + i;
        #pragma unroll
        for (int g = 0; g < 4; ++g) {
            float4 o;
            unpack2(acc[i][g * 2 + 0], o.x, o.y);
            unpack2(acc[i][g * 2 + 1], o.z, o.w);
            *(float4*)&g_sim[(size_t)b * SS + s0 + (tn + g * 16) * 4] = o;
        }
    }
}

// ---------------- K5: top-16 + softmax + proto gather -------------------
__global__ void __launch_bounds__(256) k5_topk(const float* __restrict__ mem) {
    int b = blockIdx.x, tid = threadIdx.x;
    __shared__ float cv[4096];
    __shared__ int   ci[4096];
    __shared__ float rv[256];
    __shared__ int   ri[256];
    __shared__ float selv[KTOP];
    __shared__ int   seli[KTOP];
    __shared__ float attn[KTOP];

    float vs[KTOP]; int is[KTOP];
    #pragma unroll
    for (int j = 0; j < KTOP; ++j) { vs[j] = -1e30f; is[j] = 0; }

    const float* row = g_sim + (size_t)b * SS;
    for (int s = tid; s < SS; s += 256) {
        float v = row[s];
        float mn = vs[0]; int mj = 0;
        #pragma unroll
        for (int j = 1; j < KTOP; ++j) if (vs[j] < mn) { mn = vs[j]; mj = j; }
        if (v > mn) {
            #pragma unroll
            for (int j = 0; j < KTOP; ++j) if (j == mj) { vs[j] = v; is[j] = s; }
        }
    }
    #pragma unroll
    for (int j = 0; j < KTOP; ++j) { cv[tid * KTOP + j] = vs[j]; ci[tid * KTOP + j] = is[j]; }
    __syncthreads();

    for (int r = 0; r < KTOP; ++r) {
        float mv = cv[tid * KTOP]; int mi = tid * KTOP;
        #pragma unroll
        for (int j = 1; j < KTOP; ++j)
            if (cv[tid * KTOP + j] > mv) { mv = cv[tid * KTOP + j]; mi = tid * KTOP + j; }
        rv[tid] = mv; ri[tid] = mi;
        __syncthreads();
        for (int off = 128; off; off >>= 1) {
            if (tid < off && rv[tid + off] > rv[tid]) { rv[tid] = rv[tid + off]; ri[tid] = ri[tid + off]; }
            __syncthreads();
        }
        if (tid == 0) {
            selv[r] = rv[0];
            seli[r] = ci[ri[0]];
            cv[ri[0]] = -1e30f;
        }
        __syncthreads();
    }

    if (tid == 0) {
        float mx = selv[0];           // round 0 picked the global max
        float e[KTOP], ssum = 0.f;
        #pragma unroll
        for (int k = 0; k < KTOP; ++k) { e[k] = expf(selv[k] - mx); ssum += e[k]; }
        #pragma unroll
        for (int k = 0; k < KTOP; ++k) attn[k] = e[k] / ssum;
    }
    __syncthreads();

    if (tid < 128) {
        float acc = 0.f;
        #pragma unroll
        for (int k = 0; k < KTOP; ++k)
            acc = fmaf(attn[k], mem[(size_t)seli[k] * 128 + tid], acc);
        g_proto[b * 128 + tid] = acc;
    }
}

// ---------------- K6: out = x + scale * proto (broadcast add) -----------
__global__ void __launch_bounds__(256) k6_add(const float* __restrict__ x,
                                              const float* __restrict__ scale_p,
                                              float* __restrict__ out) {
    __shared__ float pr[128];
    __shared__ float sc;
    int b = blockIdx.y;
    if (threadIdx.x < 128) pr[threadIdx.x] = g_proto[b * 128 + threadIdx.x];
    if (threadIdx.x == 0) sc = *scale_p;
    __syncthreads();

    float s = sc;
    const float4* xv = (const float4*)x;
    float4* ov = (float4*)out;
    size_t f0 = ((size_t)b * (NN * DD) + (size_t)blockIdx.x * 4096) >> 2;
    #pragma unroll
    for (int it = 0; it < 4; ++it) {
        size_t f = f0 + it * 256 + threadIdx.x;
        float4 v = xv[f];
        int d4 = (int)(f & 31);
        const float* p = &pr[d4 * 4];
        v.x = fmaf(s, p[0], v.x);
        v.y = fmaf(s, p[1], v.y);
        v.z = fmaf(s, p[2], v.z);
        v.w = fmaf(s, p[3], v.w);
        ov[f] = v;
    }
}

// ---------------- launch -------------------------------------------------
extern "C" void kernel_launch(void* const* d_in, const int* in_sizes, int n_in,
                              void* d_out, int out_size) {
    const float* x      = (const float*)d_in[0];
    const float* conv_w = (const float*)d_in[1];
    const float* conv_b = (const float*)d_in[2];
    const float* memory = (const float*)d_in[3];
    const float* scale  = (const float*)d_in[4];
    float* out = (float*)d_out;

    static int smem_set = 0;
    // NOTE: attribute set is idempotent and not a stream op; safe under capture.
    cudaFuncSetAttribute(k2_gemm, cudaFuncAttributeMaxDynamicSharedMemorySize, 102400);

    size_t smem2 = (16384 + 128 * 65) * sizeof(float);   // 98816 B

    k0_wt<<<64, 256>>>(conv_w);
    k1_mt<<<SS / 64, 256>>>(memory);
    k2_gemm<<<2048, 256, smem2>>>(x, conv_b);
    k3_q<<<BB, 128>>>();
    k4_sim<<<SS / 256, 256>>>();
    k5_topk<<<BB, 256>>>(memory);
    dim3 g6(128, BB);
    k6_add<<<g6, 256>>>(x, scale, out);
    (void)smem_set; (void)in_sizes; (void)n_in; (void)out_size;
}

// round 4
// speedup vs baseline: 1.2396x; 1.2396x over previous
#include <cuda_runtime.h>
#include <math.h>
#include <stdint.h>

#define BB 64
#define NN 4096
#define DD 128
#define SS 65536
#define KTOP 16

typedef unsigned long long ull;

// ---------------- scratch (device globals; allocation-free) ----------------
__device__ float g_mt[(size_t)DD * SS];  // normalized memory^T: [d][s]   (32 MB)
__device__ float g_qpart[BB * 2 * DD];   // per-CTA partial gelu sums
__device__ float g_qt[DD * BB];          // normalized q^T: [d][b]
__device__ float g_sim[(size_t)BB * SS]; // cosine sims                    (16 MB)
__device__ float g_proto[BB * DD];

// ---------------- generic helpers ----------------
__device__ __forceinline__ ull ffma2(ull a, ull b, ull c) {
    ull d;
    asm("fma.rn.f32x2 %0, %1, %2, %3;" : "=l"(d) : "l"(a), "l"(b), "l"(c));
    return d;
}
__device__ __forceinline__ ull dup2(float x) {
    ull d;
    asm("mov.b64 %0, {%1, %1};" : "=l"(d) : "f"(x));
    return d;
}
__device__ __forceinline__ void unpack2(ull v, float& lo, float& hi) {
    asm("mov.b64 {%0, %1}, %2;" : "=f"(lo), "=f"(hi) : "l"(v));
}
__device__ __forceinline__ float gelu_exact(float z) {
    return 0.5f * z * (1.0f + erff(z * 0.70710678118654752f));
}
__device__ __forceinline__ float tf32r(float x) {
    float y;
    asm("cvt.rna.tf32.f32 %0, %1;" : "=f"(y) : "f"(x));
    return y;
}
__device__ __forceinline__ uint32_t smem_u32(const void* p) {
    uint32_t a;
    asm("{ .reg .u64 t; cvta.to.shared.u64 t, %1; cvt.u32.u64 %0, t; }" : "=r"(a) : "l"(p));
    return a;
}
__device__ __forceinline__ void cpa16(uint32_t dst, const void* src) {
    asm volatile("cp.async.cg.shared.global [%0], [%1], 16;" :: "r"(dst), "l"(src));
}
#define CP_COMMIT() asm volatile("cp.async.commit_group;" ::: "memory")
#define CP_WAIT1()  asm volatile("cp.async.wait_group 1;" ::: "memory")
#define CP_WAIT0()  asm volatile("cp.async.wait_group 0;" ::: "memory")

// tf32 m16n8k8 mma.sync (portable PTX; lowers to HMMA fallback on sm_103)
__device__ __forceinline__ void mma_tf32(float* c, uint32_t a0, uint32_t a1,
                                         uint32_t a2, uint32_t a3,
                                         uint32_t b0, uint32_t b1) {
    asm volatile(
        "mma.sync.aligned.m16n8k8.row.col.f32.tf32.tf32.f32 "
        "{%0,%1,%2,%3}, {%4,%5,%6,%7}, {%8,%9}, {%0,%1,%2,%3};"
        : "+f"(c[0]), "+f"(c[1]), "+f"(c[2]), "+f"(c[3])
        : "r"(a0), "r"(a1), "r"(a2), "r"(a3), "r"(b0), "r"(b1));
}

// ---------------- K2: tf32 mma.sync conv1d+GeLU+sum-over-n --------------
// 128 CTAs: cta = (b, half). Each does 16 tiles of 128 positions.
// Per CTA smem: Whi/Wlo [128e][132] + x double-buffer 2x[128m][68] + bias + red.
#define WSTR 132
#define ASTR 68
#define F_WHI  0
#define F_WLO  16896
#define F_A0   33792
#define F_A1   42496
#define F_BIAS 51200
#define F_RED  51328
#define K2_SMEM ((51328 + 256) * 4)   // 206336 bytes

__global__ void __launch_bounds__(256, 1) k2_mma(const float* __restrict__ x,
                                                 const float* __restrict__ w,
                                                 const float* __restrict__ bias) {
    extern __shared__ float sm[];
    float* ws_hi = sm + F_WHI;
    float* ws_lo = sm + F_WLO;
    float* sbias = sm + F_BIAS;
    float* red   = sm + F_RED;
    uint32_t aBase[2] = { smem_u32(sm + F_A0), smem_u32(sm + F_A1) };

    int tid = threadIdx.x, wid = tid >> 5, lane = tid & 31;
    int g = lane >> 2, kc = lane & 3;
    int cta = blockIdx.x, b = cta >> 1, half = cta & 1;
    const float* xb = x + ((size_t)b * NN + (size_t)half * 2048) * DD;

    // ---- stage W split into hi/lo tf32 (exact sum) ----
    for (int i = tid; i < 4096; i += 256) {      // 4096 float4 over [128e][128d]
        float4 v = ((const float4*)w)[i];
        int e = i >> 5, c4 = (i & 31) * 4;
        float4 h, l;
        h.x = tf32r(v.x); l.x = tf32r(v.x - h.x);
        h.y = tf32r(v.y); l.y = tf32r(v.y - h.y);
        h.z = tf32r(v.z); l.z = tf32r(v.z - h.z);
        h.w = tf32r(v.w); l.w = tf32r(v.w - h.w);
        *(float4*)&ws_hi[e * WSTR + c4] = h;
        *(float4*)&ws_lo[e * WSTR + c4] = l;
    }
    if (tid < 128) sbias[tid] = bias[tid];
    __syncthreads();

    // per-thread fixed e-columns & bias
    int ew = (wid & 3) * 32;             // warp e base
    float bs[8];
    #pragma unroll
    for (int ef = 0; ef < 4; ++ef) {
        bs[ef * 2 + 0] = sbias[ew + ef * 8 + 2 * kc + 0];
        bs[ef * 2 + 1] = sbias[ew + ef * 8 + 2 * kc + 1];
    }

    float c[4][4][4];
    #pragma unroll
    for (int mf = 0; mf < 4; ++mf)
        #pragma unroll
        for (int ef = 0; ef < 4; ++ef)
            #pragma unroll
            for (int q = 0; q < 4; ++q) c[mf][ef][q] = 0.f;
    float es[8];
    #pragma unroll
    for (int s = 0; s < 8; ++s) es[s] = 0.f;

    // ---- cp.async loader: k-half h of tile t into buffer buf ----
    // half tile = 128 rows x 64 floats = 2048 float4 -> 8 per thread
    auto issue_load = [&](int t, int h, int buf) {
        const float* base = xb + (size_t)t * (128 * DD) + h * 64;
        #pragma unroll
        for (int j = 0; j < 8; ++j) {
            int idx = j * 256 + tid;             // 0..2047
            int row = idx >> 4, seg = idx & 15;
            cpa16(aBase[buf] + (uint32_t)(row * ASTR + seg * 4) * 4,
                  base + (size_t)row * DD + seg * 4);
        }
    };

    issue_load(0, 0, 0); CP_COMMIT();
    int cur = 0;
    int mrow = (wid >> 2) * 64 + g;              // A row base (m)

    #pragma unroll 1
    for (int step = 0; step < 32; ++step) {
        int h = step & 1;
        if (step < 31) {
            int ns = step + 1;
            issue_load(ns >> 1, ns & 1, cur ^ 1); CP_COMMIT(); CP_WAIT1();
        } else {
            CP_WAIT0();
        }
        __syncthreads();

        const float* A = sm + (cur ? F_A1 : F_A0);
        int kg0 = h * 64;                        // global k offset of this half
        #pragma unroll
        for (int ks = 0; ks < 8; ++ks) {
            int k0 = ks * 8 + kc;
            uint32_t a[4][4];
            #pragma unroll
            for (int mf = 0; mf < 4; ++mf) {
                int r = mrow + mf * 16;
                a[mf][0] = __float_as_uint(A[r * ASTR + k0]);
                a[mf][1] = __float_as_uint(A[(r + 8) * ASTR + k0]);
                a[mf][2] = __float_as_uint(A[r * ASTR + k0 + 4]);
                a[mf][3] = __float_as_uint(A[(r + 8) * ASTR + k0 + 4]);
            }
            #pragma unroll
            for (int ef = 0; ef < 4; ++ef) {
                int e = ew + ef * 8 + g;
                uint32_t b0 = __float_as_uint(ws_hi[e * WSTR + kg0 + k0]);
                uint32_t b1 = __float_as_uint(ws_hi[e * WSTR + kg0 + k0 + 4]);
                #pragma unroll
                for (int mf = 0; mf < 4; ++mf)
                    mma_tf32(c[mf][ef], a[mf][0], a[mf][1], a[mf][2], a[mf][3], b0, b1);
            }
            #pragma unroll
            for (int ef = 0; ef < 4; ++ef) {
                int e = ew + ef * 8 + g;
                uint32_t b0 = __float_as_uint(ws_lo[e * WSTR + kg0 + k0]);
                uint32_t b1 = __float_as_uint(ws_lo[e * WSTR + kg0 + k0 + 4]);
                #pragma unroll
                for (int mf = 0; mf < 4; ++mf)
                    mma_tf32(c[mf][ef], a[mf][0], a[mf][1], a[mf][2], a[mf][3], b0, b1);
            }
        }
        __syncthreads();
        cur ^= 1;

        if (h == 1) {
            // tile finished: gelu(feat + bias), accumulate over m, reset accums
            #pragma unroll
            for (int mf = 0; mf < 4; ++mf)
                #pragma unroll
                for (int ef = 0; ef < 4; ++ef)
                    #pragma unroll
                    for (int q = 0; q < 4; ++q) {
                        int s = ef * 2 + (q & 1);
                        es[s] += gelu_exact(c[mf][ef][q] + bs[s]);
                        c[mf][ef][q] = 0.f;
                    }
        }
    }

    // ---- reduce over m: shfl across g-groups, then across 2 m-warps ----
    #pragma unroll
    for (int off = 16; off >= 4; off >>= 1)
        #pragma unroll
        for (int s = 0; s < 8; ++s)
            es[s] += __shfl_xor_sync(0xffffffffu, es[s], off);
    if (g == 0) {
        #pragma unroll
        for (int s = 0; s < 8; ++s) {
            int ecol = ew + (s >> 1) * 8 + 2 * kc + (s & 1);
            red[(wid >> 2) * 128 + ecol] = es[s];
        }
    }
    __syncthreads();
    if (tid < 128)
        g_qpart[(b * 2 + half) * 128 + tid] = red[tid] + red[128 + tid];
}

// ---------------- K1: normalize+transpose memory -> g_mt ----------------
__global__ void __launch_bounds__(256) k1_mt(const float* __restrict__ mem) {
    __shared__ float tile[64][129];
    __shared__ float inv[64];
    int s0 = blockIdx.x * 64;
    int tid = threadIdx.x;

    int c = tid & 31, r0 = tid >> 5;
    #pragma unroll
    for (int it = 0; it < 8; ++it) {
        int r = r0 + it * 8;
        float4 v = *(const float4*)&mem[(size_t)(s0 + r) * 128 + c * 4];
        tile[r][c * 4 + 0] = v.x; tile[r][c * 4 + 1] = v.y;
        tile[r][c * 4 + 2] = v.z; tile[r][c * 4 + 3] = v.w;
    }
    __syncthreads();
    if (tid < 64) {
        float acc = 0.f;
        #pragma unroll 8
        for (int k = 0; k < 128; ++k) { float t = tile[tid][k]; acc = fmaf(t, t, acc); }
        inv[tid] = 1.0f / fmaxf(sqrtf(acc), 1e-12f);
    }
    __syncthreads();
    int r = tid & 63, kg = tid >> 6;
    float iv = inv[r];
    #pragma unroll
    for (int it = 0; it < 32; ++it) {
        int k = kg + it * 4;
        g_mt[(size_t)k * SS + s0 + r] = tile[r][k] * iv;
    }
}

// ---------------- K3: finalize q + normalize + transpose ----------------
__global__ void k3_q() {
    int b = blockIdx.x, e = threadIdx.x;
    float q = g_qpart[b * 256 + e] + g_qpart[b * 256 + 128 + e];
    __shared__ float sr[128];
    sr[e] = q * q;
    __syncthreads();
    for (int off = 64; off; off >>= 1) {
        if (e < off) sr[e] += sr[e + off];
        __syncthreads();
    }
    float inv = 1.0f / fmaxf(sqrtf(sr[0]), 1e-12f);
    g_qt[e * 64 + b] = q * inv;
}

// ---------------- K4: sim = qn @ mn^T (64 x 65536, f32x2) ---------------
__global__ void __launch_bounds__(256) k4_sim() {
    __shared__ float qs[128 * 64];
    __shared__ float ms[8 * 256];
    int tid = threadIdx.x;
    int s0 = blockIdx.x * 256;

    for (int i = tid; i < 8192; i += 256) qs[i] = g_qt[i];

    int tm = tid >> 4, tn = tid & 15;
    ull acc[4][8];
    #pragma unroll
    for (int i = 0; i < 4; ++i)
        #pragma unroll
        for (int j = 0; j < 8; ++j) acc[i][j] = 0ull;

    for (int ks = 0; ks < 16; ++ks) {
        __syncthreads();
        {
            int c = tid & 63, r = tid >> 6;
            #pragma unroll
            for (int it = 0; it < 2; ++it) {
                int r2 = r + it * 4;
                *(float4*)&ms[r2 * 256 + c * 4] =
                    *(const float4*)&g_mt[(size_t)(ks * 8 + r2) * SS + s0 + c * 4];
            }
        }
        __syncthreads();
        #pragma unroll
        for (int k = 0; k < 8; ++k) {
            float4 av = *(const float4*)&qs[(ks * 8 + k) * 64 + tm * 4];
            ull a0 = dup2(av.x), a1 = dup2(av.y), a2 = dup2(av.z), a3 = dup2(av.w);
            const float* mrow = ms + k * 256;
            #pragma unroll
            for (int gg = 0; gg < 4; ++gg) {
                ulonglong2 bv = *(const ulonglong2*)(mrow + (tn + gg * 16) * 4);
                acc[0][gg * 2 + 0] = ffma2(a0, bv.x, acc[0][gg * 2 + 0]);
                acc[0][gg * 2 + 1] = ffma2(a0, bv.y, acc[0][gg * 2 + 1]);
                acc[1][gg * 2 + 0] = ffma2(a1, bv.x, acc[1][gg * 2 + 0]);
                acc[1][gg * 2 + 1] = ffma2(a1, bv.y, acc[1][gg * 2 + 1]);
                acc[2][gg * 2 + 0] = ffma2(a2, bv.x, acc[2][gg * 2 + 0]);
                acc[2][gg * 2 + 1] = ffma2(a2, bv.y, acc[2][gg * 2 + 1]);
                acc[3][gg * 2 + 0] = ffma2(a3, bv.x, acc[3][gg * 2 + 0]);
                acc[3][gg * 2 + 1] = ffma2(a3, bv.y, acc[3][gg * 2 + 1]);
            }
        }
    }
    #pragma unroll
    for (int i = 0; i < 4; ++i) {
        int b = tm * 4 + i;
        #pragma unroll
        for (int gg = 0; gg < 4; ++gg) {
            float4 o;
            unpack2(acc[i][gg * 2 + 0], o.x, o.y);
            unpack2(acc[i][gg * 2 + 1], o.z, o.w);
            *(float4*)&g_sim[(size_t)b * SS + s0 + (tn + gg * 16) * 4] = o;
        }
    }
}

// ---------------- K5: top-16 + softmax + proto gather -------------------
__global__ void __launch_bounds__(256) k5_topk(const float* __restrict__ mem) {
    int b = blockIdx.x, tid = threadIdx.x;
    __shared__ float cv[4096];
    __shared__ int   ci[4096];
    __shared__ float rv[256];
    __shared__ int   ri[256];
    __shared__ float selv[KTOP];
    __shared__ int   seli[KTOP];
    __shared__ float attn[KTOP];

    float vs[KTOP]; int is[KTOP];
    #pragma unroll
    for (int j = 0; j < KTOP; ++j) { vs[j] = -1e30f; is[j] = 0; }

    const float* row = g_sim + (size_t)b * SS;
    for (int s = tid; s < SS; s += 256) {
        float v = row[s];
        float mn = vs[0]; int mj = 0;
        #pragma unroll
        for (int j = 1; j < KTOP; ++j) if (vs[j] < mn) { mn = vs[j]; mj = j; }
        if (v > mn) {
            #pragma unroll
            for (int j = 0; j < KTOP; ++j) if (j == mj) { vs[j] = v; is[j] = s; }
        }
    }
    #pragma unroll
    for (int j = 0; j < KTOP; ++j) { cv[tid * KTOP + j] = vs[j]; ci[tid * KTOP + j] = is[j]; }
    __syncthreads();

    for (int r = 0; r < KTOP; ++r) {
        float mv = cv[tid * KTOP]; int mi = tid * KTOP;
        #pragma unroll
        for (int j = 1; j < KTOP; ++j)
            if (cv[tid * KTOP + j] > mv) { mv = cv[tid * KTOP + j]; mi = tid * KTOP + j; }
        rv[tid] = mv; ri[tid] = mi;
        __syncthreads();
        for (int off = 128; off; off >>= 1) {
            if (tid < off && rv[tid + off] > rv[tid]) { rv[tid] = rv[tid + off]; ri[tid] = ri[tid + off]; }
            __syncthreads();
        }
        if (tid == 0) {
            selv[r] = rv[0];
            seli[r] = ci[ri[0]];
            cv[ri[0]] = -1e30f;
        }
        __syncthreads();
    }

    if (tid == 0) {
        float mx = selv[0];
        float e[KTOP], ssum = 0.f;
        #pragma unroll
        for (int k = 0; k < KTOP; ++k) { e[k] = expf(selv[k] - mx); ssum += e[k]; }
        #pragma unroll
        for (int k = 0; k < KTOP; ++k) attn[k] = e[k] / ssum;
    }
    __syncthreads();

    if (tid < 128) {
        float acc = 0.f;
        #pragma unroll
        for (int k = 0; k < KTOP; ++k)
            acc = fmaf(attn[k], mem[(size_t)seli[k] * 128 + tid], acc);
        g_proto[b * 128 + tid] = acc;
    }
}

// ---------------- K6: out = x + scale * proto ---------------------------
__global__ void __launch_bounds__(256) k6_add(const float* __restrict__ x,
                                              const float* __restrict__ scale_p,
                                              float* __restrict__ out) {
    __shared__ float pr[128];
    __shared__ float sc;
    int b = blockIdx.y;
    if (threadIdx.x < 128) pr[threadIdx.x] = g_proto[b * 128 + threadIdx.x];
    if (threadIdx.x == 0) sc = *scale_p;
    __syncthreads();

    float s = sc;
    const float4* xv = (const float4*)x;
    float4* ov = (float4*)out;
    size_t f0 = ((size_t)b * (NN * DD) + (size_t)blockIdx.x * 4096) >> 2;
    #pragma unroll
    for (int it = 0; it < 4; ++it) {
        size_t f = f0 + it * 256 + threadIdx.x;
        float4 v = xv[f];
        int d4 = (int)(f & 31);
        const float* p = &pr[d4 * 4];
        v.x = fmaf(s, p[0], v.x);
        v.y = fmaf(s, p[1], v.y);
        v.z = fmaf(s, p[2], v.z);
        v.w = fmaf(s, p[3], v.w);
        ov[f] = v;
    }
}

// ---------------- launch -------------------------------------------------
extern "C" void kernel_launch(void* const* d_in, const int* in_sizes, int n_in,
                              void* d_out, int out_size) {
    const float* x      = (const float*)d_in[0];
    const float* conv_w = (const float*)d_in[1];
    const float* conv_b = (const float*)d_in[2];
    const float* memory = (const float*)d_in[3];
    const float* scale  = (const float*)d_in[4];
    float* out = (float*)d_out;

    cudaFuncSetAttribute(k2_mma, cudaFuncAttributeMaxDynamicSharedMemorySize, K2_SMEM);

    k2_mma<<<128, 256, K2_SMEM>>>(x, conv_w, conv_b);
    k1_mt<<<SS / 64, 256>>>(memory);
    k3_q<<<BB, 128>>>();
    k4_sim<<<SS / 256, 256>>>();
    k5_topk<<<BB, 256>>>(memory);
    dim3 g6(128, BB);
    k6_add<<<g6, 256>>>(x, scale, out);
    (void)in_sizes; (void)n_in; (void)out_size;
}